// round 12
// baseline (speedup 1.0000x reference)
#include <cuda_runtime.h>

// ---------------------------------------------------------------------------
// Fused LSTMMeasurementPredictor — round 12
//   B=131072, H=128, NQ=2, P=32, D_IN=17, T=16
// R11 structure (warp-specialized dual chains, pinned small-GEMM weights,
// act+weight prefetch). NEW lstm_step tiling: thread owns 2 weight cols
// (gates i,f or g,o of one unit) x ALL 32 batches -> dup-MOVs halved,
// weight LDG bytes halved (row fetched once per group per k). Gate halves
// recombined in the epilogue via lane-pair shfl_xor(1).
// ---------------------------------------------------------------------------

#define NTH 512
#define BT  32
#define SS  36   // padded row stride; (36*4)%16==0, conflict-free LDS.128

constexpr int OFF_XA  = 0;                   // 17  rows : x ping
constexpr int OFF_XB  = OFF_XA  + 17  * SS;  // 17  rows : x pong
constexpr int OFF_HCA = OFF_XB  + 17  * SS;  // 128 rows : cell h ping
constexpr int OFF_HCB = OFF_HCA + 128 * SS;  // 128 rows : cell h pong
constexpr int OFF_S   = OFF_HCB + 128 * SS;  // 128 rows : group-B s staging
constexpr int OFF_CC  = OFF_S   + 128 * SS;  // 128 rows : cell c
constexpr int OFF_H0  = OFF_CC  + 128 * SS;  // 32  rows : lstm0 proj h
constexpr int OFF_C0  = OFF_H0  + 32  * SS;  // 128 rows : lstm0 c
constexpr int OFF_H1  = OFF_C0  + 128 * SS;  // 32  rows : lstm1 proj h
constexpr int OFF_C1  = OFF_H1  + 32  * SS;  // 128 rows : lstm1 c
constexpr int OFF_RHO = OFF_C1  + 128 * SS;  // 32*33    : rho
constexpr int OFF_V   = OFF_RHO + 32 * 33;   // 8 rows   : projector v
// duplicated-pair small-GEMM weights (filled once per CTA):
constexpr int OFF_PW0 = OFF_V   + 8 * SS;    // 128*64 : Whr0T dup'd
constexpr int OFF_PW1 = OFF_PW0 + 128 * 64;  // 128*64 : Whr1T dup'd
constexpr int OFF_PWP = OFF_PW1 + 128 * 64;  // 128*16 : WpT dup'd
constexpr int SMEM_FLOATS = OFF_PWP + 128 * 16;
constexpr int SMEM_BYTES  = SMEM_FLOATS * 4; // ~199 KB

// compact packed weights: W[k][512], column jp = u*4 + gate (i,f,g,o).
// +1024 floats pad so the distance-2 prefetch can overshoot by 2 rows.
__device__ __align__(16) float g_Wc[145 * 512 + 1024];
__device__ __align__(16) float g_bc[512];
__device__ __align__(16) float g_W0[49 * 512 + 1024];
__device__ __align__(16) float g_b0[512];
__device__ __align__(16) float g_W1[64 * 512 + 1024];
__device__ __align__(16) float g_b1[512];
__device__ __align__(16) float g_Whr0T[128 * 32];   // [k][n] compact
__device__ __align__(16) float g_Whr1T[128 * 32];
__device__ __align__(16) float g_WpT[128 * 8];      // [k][n] compact

__global__ void prep_kernel(
    const float* __restrict__ Wihc, const float* __restrict__ Whhc,
    const float* __restrict__ bihc, const float* __restrict__ bhhc,
    const float* __restrict__ Wp,
    const float* __restrict__ Wih0, const float* __restrict__ Whh0,
    const float* __restrict__ bih0, const float* __restrict__ bhh0,
    const float* __restrict__ Whr0,
    const float* __restrict__ Wih1, const float* __restrict__ Whh1,
    const float* __restrict__ bih1, const float* __restrict__ bhh1,
    const float* __restrict__ Whr1)
{
    int i0 = blockIdx.x * blockDim.x + threadIdx.x;
    int stride = gridDim.x * blockDim.x;

    for (int i = i0; i < 145 * 512; i += stride) {
        int k = i >> 9, jp = i & 511;
        int u = jp >> 2, g = jp & 3, j = g * 128 + u;
        g_Wc[i] = (k < 17) ? Wihc[j * 17 + k] : Whhc[j * 128 + (k - 17)];
    }
    for (int i = i0; i < 49 * 512; i += stride) {
        int k = i >> 9, jp = i & 511;
        int u = jp >> 2, g = jp & 3, j = g * 128 + u;
        g_W0[i] = (k < 17) ? Wih0[j * 17 + k] : Whh0[j * 32 + (k - 17)];
    }
    for (int i = i0; i < 64 * 512; i += stride) {
        int k = i >> 9, jp = i & 511;
        int u = jp >> 2, g = jp & 3, j = g * 128 + u;
        g_W1[i] = (k < 32) ? Wih1[j * 32 + k] : Whh1[j * 32 + (k - 32)];
    }
    for (int i = i0; i < 1024; i += stride) {
        g_Wc[145 * 512 + i] = 0.f;
        g_W0[49 * 512 + i] = 0.f;
        g_W1[64 * 512 + i] = 0.f;
    }
    for (int i = i0; i < 512; i += stride) {
        int u = i >> 2, g = i & 3, j = g * 128 + u;
        g_bc[i] = bihc[j] + bhhc[j];
        g_b0[i] = bih0[j] + bhh0[j];
        g_b1[i] = bih1[j] + bhh1[j];
    }
    for (int i = i0; i < 128 * 32; i += stride) {
        int k = i >> 5, n = i & 31;
        g_Whr0T[i] = Whr0[n * 128 + k];
        g_Whr1T[i] = Whr1[n * 128 + k];
    }
    for (int i = i0; i < 128 * 8; i += stride) {
        int k = i >> 3, n = i & 7;
        g_WpT[i] = Wp[n * 128 + k];
    }
}

// ---------------------------------------------------------------------------
typedef unsigned long long ull;

__device__ __forceinline__ void fma2(ull& acc, ull a, ull b) {
    asm("fma.rn.f32x2 %0, %1, %2, %0;" : "+l"(acc) : "l"(a), "l"(b));
}
__device__ __forceinline__ ull dup2(float x) {
    ull r;
    asm("mov.b64 %0, {%1, %1};" : "=l"(r) : "f"(x));
    return r;
}
__device__ __forceinline__ void unpk(ull v, float& lo, float& hi) {
    asm("mov.b64 {%0, %1}, %2;" : "=f"(lo), "=f"(hi) : "l"(v));
}
#define BARA() asm volatile("bar.sync 1, 256;" ::: "memory")
#define BARB() asm volatile("bar.sync 2, 256;" ::: "memory")

__device__ __forceinline__ float fsig(float x) {
    return __fdividef(1.0f, 1.0f + __expf(-x));
}
__device__ __forceinline__ float ftanh(float x) {
    return __fdividef(2.0f, 1.0f + __expf(-2.0f * x)) - 1.0f;
}

// LSTM step: G[32,512] = [A(KA); B(KB)] @ W + bias, then gate update.
// 256-thread collective. Thread gtid owns weight cols (2*gtid, 2*gtid+1):
//   parity = gtid&1 == 0 -> gates (i,f) of unit m = gtid>>1
//   parity = gtid&1 == 1 -> gates (g,o) of unit m
// for ALL 32 batches: acc[c][p], p = batch pair (2p,2p+1), 32 ull accs.
// Per k: 1 LDG.64 (2 cols) + 2 dup2 + 8 LDS.128 (full act row, broadcast)
// + 32 FFMA2. Weight prefetch distance 2, act prefetch distance 1.
// Epilogue recombines the 4 gates of unit m via lane-pair shfl_xor(1):
// even lane keeps batches 0..15, odd lane batches 16..31.
template <int KA, int KB>
__device__ __forceinline__ void lstm_step(
    const float* __restrict__ W, const float* __restrict__ bias,
    const float* shA, const float* shB, float* shC, float* shOut,
    int gtid)
{
    const int m      = gtid >> 1;
    const int parity = gtid & 1;

    ull acc[2][16];
    {
        float2 bs = __ldg((const float2*)(bias + 2 * gtid));
        ull d0 = dup2(bs.x), d1 = dup2(bs.y);
#pragma unroll
        for (int p = 0; p < 16; ++p) { acc[0][p] = d0; acc[1][p] = d1; }
    }
    const float* Wk = W + 2 * gtid;       // weight ptr (cols 2gtid,2gtid+1)
    const float* ap = shA;                // act row ptr (full row)

    float2 w0 = __ldg((const float2*)(Wk));
    float2 w1 = __ldg((const float2*)(Wk + 512));
    ulonglong2 a0 = *(const ulonglong2*)(ap);
    ulonglong2 a1 = *(const ulonglong2*)(ap + 4);
    ulonglong2 a2 = *(const ulonglong2*)(ap + 8);
    ulonglong2 a3 = *(const ulonglong2*)(ap + 12);
    ulonglong2 a4 = *(const ulonglong2*)(ap + 16);
    ulonglong2 a5 = *(const ulonglong2*)(ap + 20);
    ulonglong2 a6 = *(const ulonglong2*)(ap + 24);
    ulonglong2 a7 = *(const ulonglong2*)(ap + 28);

#define LSTM_BODY(APN)                                                        \
    {                                                                         \
        float2 wn = __ldg((const float2*)(Wk + 1024));                        \
        const float* apn_ = (APN);                                            \
        ulonglong2 n0 = *(const ulonglong2*)(apn_);                           \
        ulonglong2 n1 = *(const ulonglong2*)(apn_ + 4);                       \
        ulonglong2 n2 = *(const ulonglong2*)(apn_ + 8);                       \
        ulonglong2 n3 = *(const ulonglong2*)(apn_ + 12);                      \
        ulonglong2 n4 = *(const ulonglong2*)(apn_ + 16);                      \
        ulonglong2 n5 = *(const ulonglong2*)(apn_ + 20);                      \
        ulonglong2 n6 = *(const ulonglong2*)(apn_ + 24);                      \
        ulonglong2 n7 = *(const ulonglong2*)(apn_ + 28);                      \
        ull wd0 = dup2(w0.x), wd1 = dup2(w0.y);                               \
        fma2(acc[0][0],  wd0, a0.x); fma2(acc[0][1],  wd0, a0.y);             \
        fma2(acc[0][2],  wd0, a1.x); fma2(acc[0][3],  wd0, a1.y);             \
        fma2(acc[0][4],  wd0, a2.x); fma2(acc[0][5],  wd0, a2.y);             \
        fma2(acc[0][6],  wd0, a3.x); fma2(acc[0][7],  wd0, a3.y);             \
        fma2(acc[0][8],  wd0, a4.x); fma2(acc[0][9],  wd0, a4.y);             \
        fma2(acc[0][10], wd0, a5.x); fma2(acc[0][11], wd0, a5.y);             \
        fma2(acc[0][12], wd0, a6.x); fma2(acc[0][13], wd0, a6.y);             \
        fma2(acc[0][14], wd0, a7.x); fma2(acc[0][15], wd0, a7.y);             \
        fma2(acc[1][0],  wd1, a0.x); fma2(acc[1][1],  wd1, a0.y);             \
        fma2(acc[1][2],  wd1, a1.x); fma2(acc[1][3],  wd1, a1.y);             \
        fma2(acc[1][4],  wd1, a2.x); fma2(acc[1][5],  wd1, a2.y);             \
        fma2(acc[1][6],  wd1, a3.x); fma2(acc[1][7],  wd1, a3.y);             \
        fma2(acc[1][8],  wd1, a4.x); fma2(acc[1][9],  wd1, a4.y);             \
        fma2(acc[1][10], wd1, a5.x); fma2(acc[1][11], wd1, a5.y);             \
        fma2(acc[1][12], wd1, a6.x); fma2(acc[1][13], wd1, a6.y);             \
        fma2(acc[1][14], wd1, a7.x); fma2(acc[1][15], wd1, a7.y);             \
        w0 = w1; w1 = wn; Wk += 512;                                          \
        a0 = n0; a1 = n1; a2 = n2; a3 = n3;                                   \
        a4 = n4; a5 = n5; a6 = n6; a7 = n7;                                   \
    }

    // KA segment (iterations 0..KA-2): next act row is ap+SS
#pragma unroll 4
    for (int k = 0; k < KA - 1; ++k) {
        LSTM_BODY(ap + SS);
        ap += SS;
    }
    // transition iteration (k = KA-1): next act row is shB row 0
    LSTM_BODY(shB);
    ap = shB;
    // KB segment (last prefetch overshoots 1 row — safe by layout)
#pragma unroll 8
    for (int k = 0; k < KB; ++k) {
        LSTM_BODY(ap + SS);
        ap += SS;
    }
#undef LSTM_BODY

    // ---- gate exchange: lanes (2i, 2i+1) hold (i,f) and (g,o) of unit m.
    // even lane keeps batch pairs q=0..7 (batches 0..15), odd keeps q=8..15.
    // each lane sends the 8 pairs its partner will process.
    ull r0[8], r1[8];
#pragma unroll
    for (int j = 0; j < 8; ++j) {
        ull s0 = parity ? acc[0][j] : acc[0][j + 8];
        ull s1 = parity ? acc[1][j] : acc[1][j + 8];
        r0[j] = __shfl_xor_sync(0xFFFFFFFFu, s0, 1);
        r1[j] = __shfl_xor_sync(0xFFFFFFFFu, s1, 1);
    }

    // epilogue: 16 batches per thread (bbase = parity*16)
    const int bbase = parity * 16;
    float cb[16], sb[16];
    {
        const float* cp_ = shC + m * SS + bbase;
#pragma unroll
        for (int j = 0; j < 4; ++j) {
            float4 cv = *(const float4*)(cp_ + 4 * j);
            cb[4 * j] = cv.x; cb[4 * j + 1] = cv.y;
            cb[4 * j + 2] = cv.z; cb[4 * j + 3] = cv.w;
        }
    }
#pragma unroll
    for (int j = 0; j < 8; ++j) {
        // own cols at q = bbase/2 + j :
        ull A0 = parity ? acc[0][j + 8] : acc[0][j];
        ull A1 = parity ? acc[1][j + 8] : acc[1][j];
        ull iF = parity ? r0[j] : A0;      // gate i
        ull fF = parity ? r1[j] : A1;      // gate f
        ull gF = parity ? A0 : r0[j];      // gate g
        ull oF = parity ? A1 : r1[j];      // gate o
        float i0, i1, f0, f1, g0, g1, o0, o1;
        unpk(iF, i0, i1); unpk(fF, f0, f1);
        unpk(gF, g0, g1); unpk(oF, o0, o1);
        float cn0 = fsig(f0) * cb[2 * j]     + fsig(i0) * ftanh(g0);
        float cn1 = fsig(f1) * cb[2 * j + 1] + fsig(i1) * ftanh(g1);
        cb[2 * j]     = cn0;
        cb[2 * j + 1] = cn1;
        sb[2 * j]     = fsig(o0) * ftanh(cn0);
        sb[2 * j + 1] = fsig(o1) * ftanh(cn1);
    }
    {
        float* cp_ = shC + m * SS + bbase;
        float* op_ = shOut + m * SS + bbase;
#pragma unroll
        for (int j = 0; j < 4; ++j) {
            *(float4*)(cp_ + 4 * j) =
                make_float4(cb[4 * j], cb[4 * j + 1], cb[4 * j + 2], cb[4 * j + 3]);
            *(float4*)(op_ + 4 * j) =
                make_float4(sb[4 * j], sb[4 * j + 1], sb[4 * j + 2], sb[4 * j + 3]);
        }
    }
}

// hp[32,32] = s[32,128] @ WhrT[128,32], weights dup'd in SMEM (stride 64).
// 256-thread collective: cg = gtid&15 -> cols 2cg,2cg+1;
// p = gtid>>4 -> batches 2p, 2p+1. Pure LDS + FFMA2.
__device__ __forceinline__ void proj_gemm(
    const float* sPW, const float* shS, float* shHdst,
    float* outp, int gtid)
{
    const int cg = gtid & 15;
    const int p  = gtid >> 4;
    ull acc0 = 0ull, acc1 = 0ull;
    const float* Wu = sPW + 4 * cg;
#pragma unroll 8
    for (int k = 0; k < 128; ++k) {
        ulonglong2 w = *(const ulonglong2*)(Wu + k * 64);  // (wc0,wc0),(wc1,wc1)
        ull a = *(const ull*)(shS + k * SS + 2 * p);       // (s_b0, s_b1)
        fma2(acc0, w.x, a);
        fma2(acc1, w.y, a);
    }
    float v00, v10, v01, v11;   // v[b][c]
    unpk(acc0, v00, v10);
    unpk(acc1, v01, v11);
    float* hp = shHdst + (2 * cg) * SS + 2 * p;
    hp[0] = v00; hp[1] = v10;
    hp[SS] = v01; hp[SS + 1] = v11;
    if (outp) {
        *(float2*)(outp + (size_t)(2 * p) * 512 + 2 * cg)     = make_float2(v00, v01);
        *(float2*)(outp + (size_t)(2 * p + 1) * 512 + 2 * cg) = make_float2(v10, v11);
    }
}

// v[8,32] = h_new[32,128] @ WpT[128,8] + bp, weights dup'd in SMEM (stride 16).
// 128 active threads: nn = gtid&7 (one col), p = gtid>>3 (batches 2p,2p+1).
__device__ __forceinline__ void wp_gemm(
    const float* __restrict__ bp, const float* sPWP,
    const float* shS, float* shV, int gtid)
{
    if (gtid >= 128) return;
    const int nn = gtid & 7;
    const int p  = gtid >> 3;
    ull acc = dup2(__ldg(&bp[nn]));
    const float* Wu = sPWP + 2 * nn;
#pragma unroll 8
    for (int k = 0; k < 128; ++k) {
        ull w = *(const ull*)(Wu + k * 16);
        ull a = *(const ull*)(shS + k * SS + 2 * p);
        fma2(acc, w, a);
    }
    float lo, hi;
    unpk(acc, lo, hi);
    shV[nn * SS + 2 * p]     = lo;
    shV[nn * SS + 2 * p + 1] = hi;
}

// quantum measurement physics for one batch element b (0..31); writes xnext
__device__ __forceinline__ void physics(const float* shV, const float* shRHO,
                                        float* shX, int b)
{
    float Mr[2][2][2], Mi[2][2][2];
#pragma unroll
    for (int q = 0; q < 2; ++q) {
        float ar = shV[(q * 4 + 0) * SS + b];
        float ai = shV[(q * 4 + 1) * SS + b];
        float br = shV[(q * 4 + 2) * SS + b];
        float bi = shV[(q * 4 + 3) * SS + b];
        float n00 = ar * ar + ai * ai;
        float n11 = br * br + bi * bi;
        float inv = 1.0f / (n00 + n11);
        float pr = (ar * br + ai * bi) * inv;
        float pi = (ai * br - ar * bi) * inv;
        Mr[q][0][0] = n00 * inv; Mi[q][0][0] = 0.f;
        Mr[q][0][1] = pr;        Mi[q][0][1] = pi;
        Mr[q][1][0] = pr;        Mi[q][1][0] = -pi;
        Mr[q][1][1] = n11 * inv; Mi[q][1][1] = 0.f;
    }
    const float* rp = shRHO + b * 33;
    float m = 0.f;
#pragma unroll
    for (int a = 0; a < 2; ++a)
#pragma unroll
        for (int c = 0; c < 2; ++c)
#pragma unroll
            for (int b2 = 0; b2 < 2; ++b2)
#pragma unroll
                for (int d = 0; d < 2; ++d) {
                    float tr_ = Mr[0][a][c] * Mr[1][b2][d] - Mi[0][a][c] * Mi[1][b2][d];
                    float ti_ = Mr[0][a][c] * Mi[1][b2][d] + Mi[0][a][c] * Mr[1][b2][d];
                    int row = c * 2 + d, col = a * 2 + b2;
                    float rr = rp[row * 4 + col];
                    float ri = rp[16 + row * 4 + col];
                    m += tr_ * rr - ti_ * ri;
                }
    shX[0 * SS + b] = m;
#pragma unroll
    for (int q = 0; q < 2; ++q)
#pragma unroll
        for (int i = 0; i < 2; ++i)
#pragma unroll
            for (int j = 0; j < 2; ++j) {
                int base = 1 + 8 * q + 4 * i + 2 * j;
                shX[base * SS + b]       = Mr[q][i][j];
                shX[(base + 1) * SS + b] = Mi[q][i][j];
            }
}

__global__ void __launch_bounds__(NTH, 1) fused_kernel(
    const float* __restrict__ meas, const float* __restrict__ basis_r,
    const float* __restrict__ basis_i, const float* __restrict__ rho,
    const float* __restrict__ h0in, const float* __restrict__ c0in,
    const float* __restrict__ bp, float* __restrict__ out)
{
    extern __shared__ float sm[];
    float* shS   = sm + OFF_S;
    float* shCC  = sm + OFF_CC;
    float* shH0  = sm + OFF_H0;
    float* shC0  = sm + OFF_C0;
    float* shH1  = sm + OFF_H1;
    float* shC1  = sm + OFF_C1;
    float* shRHO = sm + OFF_RHO;
    float* shV   = sm + OFF_V;
    float* sPW0  = sm + OFF_PW0;
    float* sPW1  = sm + OFF_PW1;
    float* sPWP  = sm + OFF_PWP;

    const int tid = threadIdx.x;
    const int b0g = blockIdx.x * BT;

    // ---- init loads into XA ----
    for (int i = tid; i < BT; i += NTH)
        sm[OFF_XA + 0 * SS + i] = meas[b0g + i];
    for (int i = tid; i < BT * 8; i += NTH) {
        int b = i >> 3, e = i & 7;
        sm[OFF_XA + (1 + 2 * e) * SS + b] = basis_r[(size_t)(b0g + b) * 8 + e];
        sm[OFF_XA + (2 + 2 * e) * SS + b] = basis_i[(size_t)(b0g + b) * 8 + e];
    }
    for (int i = tid; i < BT * 32; i += NTH) {
        int b = i >> 5, e = i & 31;
        shRHO[b * 33 + e] = rho[(size_t)(b0g + b) * 32 + e];
    }
    for (int i = tid; i < BT * 128; i += NTH) {
        int b = i >> 7, u = i & 127;
        sm[OFF_HCA + u * SS + b] = h0in[(size_t)(b0g + b) * 128 + u];
        shCC[u * SS + b]         = c0in[(size_t)(b0g + b) * 128 + u];
    }
    // zero H0, C0, H1, C1 (320 contiguous rows)
    for (int i = tid; i < 320 * SS; i += NTH)
        sm[OFF_H0 + i] = 0.f;
    // fill dup'd small-GEMM weights (once per CTA)
    for (int i = tid; i < 128 * 32; i += NTH) {
        int k = i >> 5, n = i & 31;
        float v0 = __ldg(&g_Whr0T[i]);
        float v1 = __ldg(&g_Whr1T[i]);
        sPW0[k * 64 + 2 * n] = v0; sPW0[k * 64 + 2 * n + 1] = v0;
        sPW1[k * 64 + 2 * n] = v1; sPW1[k * 64 + 2 * n + 1] = v1;
    }
    for (int i = tid; i < 128 * 8; i += NTH) {
        int k = i >> 3, n = i & 7;
        float v = __ldg(&g_WpT[i]);
        sPWP[k * 16 + 2 * n] = v; sPWP[k * 16 + 2 * n + 1] = v;
    }
    __syncthreads();

    const bool isA = (tid < 256);
    const int gtid = tid & 255;

    float* xcur = sm + OFF_XA;
    float* xnxt = sm + OFF_XB;
    float* hcur = sm + OFF_HCA;
    float* hnxt = sm + OFF_HCB;

    for (int t = 0; t < 16; ++t) {
        if (isA) {
            // group A: cell chain (produces x_{t+1} into xnxt, h_new into hnxt)
            if (t < 15) {
                lstm_step<17, 128>(g_Wc, g_bc, xcur, hcur, shCC, hnxt, gtid);
                BARA();
                wp_gemm(bp, sPWP, hnxt, shV, gtid);
                BARA();
                if (gtid < BT) physics(shV, shRHO, xnxt, gtid);
            }
        } else {
            // group B: output chain for step t (reads xcur only)
            lstm_step<17, 32>(g_W0, g_b0, xcur, shH0, shC0, shS, gtid);
            BARB();
            proj_gemm(sPW0, shS, shH0, nullptr, gtid);
            BARB();
            lstm_step<32, 32>(g_W1, g_b1, shH0, shH1, shC1, shS, gtid);
            BARB();
            proj_gemm(sPW1, shS, shH1,
                      out + (size_t)b0g * 512 + (size_t)t * 32, gtid);
        }
        __syncthreads();
        if (t < 15) {
            float* tp = hcur; hcur = hnxt; hnxt = tp;
            float* tx = xcur; xcur = xnxt; xnxt = tx;
        }
    }
}

extern "C" void kernel_launch(void* const* d_in, const int* in_sizes, int n_in,
                              void* d_out, int out_size)
{
    const float* meas   = (const float*)d_in[0];
    const float* br     = (const float*)d_in[1];
    const float* bi     = (const float*)d_in[2];
    const float* rho    = (const float*)d_in[3];
    const float* h0     = (const float*)d_in[4];
    const float* c0     = (const float*)d_in[5];
    const float* Wihc   = (const float*)d_in[6];
    const float* Whhc   = (const float*)d_in[7];
    const float* bihc   = (const float*)d_in[8];
    const float* bhhc   = (const float*)d_in[9];
    const float* Wp     = (const float*)d_in[10];
    const float* bp     = (const float*)d_in[11];
    const float* Wih0   = (const float*)d_in[12];
    const float* Whh0   = (const float*)d_in[13];
    const float* bih0   = (const float*)d_in[14];
    const float* bhh0   = (const float*)d_in[15];
    const float* Whr0   = (const float*)d_in[16];
    const float* Wih1   = (const float*)d_in[17];
    const float* Whh1   = (const float*)d_in[18];
    const float* bih1   = (const float*)d_in[19];
    const float* bhh1   = (const float*)d_in[20];
    const float* Whr1   = (const float*)d_in[21];

    int B = in_sizes[0];
    int nblocks = B / BT;

    cudaFuncSetAttribute(fused_kernel,
                         cudaFuncAttributeMaxDynamicSharedMemorySize,
                         SMEM_BYTES);

    prep_kernel<<<128, 256>>>(Wihc, Whhc, bihc, bhhc, Wp,
                              Wih0, Whh0, bih0, bhh0, Whr0,
                              Wih1, Whh1, bih1, bhh1, Whr1);

    fused_kernel<<<nblocks, NTH, SMEM_BYTES>>>(
        meas, br, bi, rho, h0, c0, bp, (float*)d_out);
}

// round 13
// speedup vs baseline: 1.2281x; 1.2281x over previous
#include <cuda_runtime.h>

// ---------------------------------------------------------------------------
// Fused LSTMMeasurementPredictor — round 13
//   = round 11 (best: 12.33 ms) + MUFU.TANH nonlinearities.
// Warp-specialized dual chains, pinned small-GEMM weights, act+weight
// prefetch, split KA/KB k-loop with pointer bumps. Gate nonlinearities now
// use tanh.approx.f32 (1 MUFU) — sigmoid via 0.5*tanh(x/2)+0.5.
// ---------------------------------------------------------------------------

#define NTH 512
#define BT  32
#define SS  36   // padded row stride; (36*4)%16==0, conflict-free LDS.128

constexpr int OFF_XA  = 0;                   // 17  rows : x ping
constexpr int OFF_XB  = OFF_XA  + 17  * SS;  // 17  rows : x pong
constexpr int OFF_HCA = OFF_XB  + 17  * SS;  // 128 rows : cell h ping
constexpr int OFF_HCB = OFF_HCA + 128 * SS;  // 128 rows : cell h pong
constexpr int OFF_S   = OFF_HCB + 128 * SS;  // 128 rows : group-B s staging
constexpr int OFF_CC  = OFF_S   + 128 * SS;  // 128 rows : cell c
constexpr int OFF_H0  = OFF_CC  + 128 * SS;  // 32  rows : lstm0 proj h
constexpr int OFF_C0  = OFF_H0  + 32  * SS;  // 128 rows : lstm0 c
constexpr int OFF_H1  = OFF_C0  + 128 * SS;  // 32  rows : lstm1 proj h
constexpr int OFF_C1  = OFF_H1  + 32  * SS;  // 128 rows : lstm1 c
constexpr int OFF_RHO = OFF_C1  + 128 * SS;  // 32*33    : rho
constexpr int OFF_V   = OFF_RHO + 32 * 33;   // 8 rows   : projector v
// duplicated-pair small-GEMM weights (filled once per CTA):
constexpr int OFF_PW0 = OFF_V   + 8 * SS;    // 128*64 : Whr0T dup'd
constexpr int OFF_PW1 = OFF_PW0 + 128 * 64;  // 128*64 : Whr1T dup'd
constexpr int OFF_PWP = OFF_PW1 + 128 * 64;  // 128*16 : WpT dup'd
constexpr int SMEM_FLOATS = OFF_PWP + 128 * 16;
constexpr int SMEM_BYTES  = SMEM_FLOATS * 4; // ~199 KB

// compact packed weights: W[k][512], column jp = u*4 + gate (i,f,g,o).
// +1024 floats pad so the distance-2 prefetch can overshoot by 2 rows.
__device__ __align__(16) float g_Wc[145 * 512 + 1024];
__device__ __align__(16) float g_bc[512];
__device__ __align__(16) float g_W0[49 * 512 + 1024];
__device__ __align__(16) float g_b0[512];
__device__ __align__(16) float g_W1[64 * 512 + 1024];
__device__ __align__(16) float g_b1[512];
__device__ __align__(16) float g_Whr0T[128 * 32];   // [k][n] compact
__device__ __align__(16) float g_Whr1T[128 * 32];
__device__ __align__(16) float g_WpT[128 * 8];      // [k][n] compact

__global__ void prep_kernel(
    const float* __restrict__ Wihc, const float* __restrict__ Whhc,
    const float* __restrict__ bihc, const float* __restrict__ bhhc,
    const float* __restrict__ Wp,
    const float* __restrict__ Wih0, const float* __restrict__ Whh0,
    const float* __restrict__ bih0, const float* __restrict__ bhh0,
    const float* __restrict__ Whr0,
    const float* __restrict__ Wih1, const float* __restrict__ Whh1,
    const float* __restrict__ bih1, const float* __restrict__ bhh1,
    const float* __restrict__ Whr1)
{
    int i0 = blockIdx.x * blockDim.x + threadIdx.x;
    int stride = gridDim.x * blockDim.x;

    for (int i = i0; i < 145 * 512; i += stride) {
        int k = i >> 9, jp = i & 511;
        int u = jp >> 2, g = jp & 3, j = g * 128 + u;
        g_Wc[i] = (k < 17) ? Wihc[j * 17 + k] : Whhc[j * 128 + (k - 17)];
    }
    for (int i = i0; i < 49 * 512; i += stride) {
        int k = i >> 9, jp = i & 511;
        int u = jp >> 2, g = jp & 3, j = g * 128 + u;
        g_W0[i] = (k < 17) ? Wih0[j * 17 + k] : Whh0[j * 32 + (k - 17)];
    }
    for (int i = i0; i < 64 * 512; i += stride) {
        int k = i >> 9, jp = i & 511;
        int u = jp >> 2, g = jp & 3, j = g * 128 + u;
        g_W1[i] = (k < 32) ? Wih1[j * 32 + k] : Whh1[j * 32 + (k - 32)];
    }
    for (int i = i0; i < 1024; i += stride) {
        g_Wc[145 * 512 + i] = 0.f;
        g_W0[49 * 512 + i] = 0.f;
        g_W1[64 * 512 + i] = 0.f;
    }
    for (int i = i0; i < 512; i += stride) {
        int u = i >> 2, g = i & 3, j = g * 128 + u;
        g_bc[i] = bihc[j] + bhhc[j];
        g_b0[i] = bih0[j] + bhh0[j];
        g_b1[i] = bih1[j] + bhh1[j];
    }
    for (int i = i0; i < 128 * 32; i += stride) {
        int k = i >> 5, n = i & 31;
        g_Whr0T[i] = Whr0[n * 128 + k];
        g_Whr1T[i] = Whr1[n * 128 + k];
    }
    for (int i = i0; i < 128 * 8; i += stride) {
        int k = i >> 3, n = i & 7;
        g_WpT[i] = Wp[n * 128 + k];
    }
}

// ---------------------------------------------------------------------------
typedef unsigned long long ull;

__device__ __forceinline__ void fma2(ull& acc, ull a, ull b) {
    asm("fma.rn.f32x2 %0, %1, %2, %0;" : "+l"(acc) : "l"(a), "l"(b));
}
__device__ __forceinline__ ull dup2(float x) {
    ull r;
    asm("mov.b64 %0, {%1, %1};" : "=l"(r) : "f"(x));
    return r;
}
__device__ __forceinline__ void unpk(ull v, float& lo, float& hi) {
    asm("mov.b64 {%0, %1}, %2;" : "=f"(lo), "=f"(hi) : "l"(v));
}
#define BARA() asm volatile("bar.sync 1, 256;" ::: "memory")
#define BARB() asm volatile("bar.sync 2, 256;" ::: "memory")

// HW tanh (MUFU.TANH, sm_75+): 1 MUFU op, rel err ~2^-10.5
__device__ __forceinline__ float htanh(float x) {
    float y;
    asm("tanh.approx.f32 %0, %1;" : "=f"(y) : "f"(x));
    return y;
}
__device__ __forceinline__ float fsig(float x) {
    return fmaf(0.5f, htanh(0.5f * x), 0.5f);
}
__device__ __forceinline__ float ftanh(float x) {
    return htanh(x);
}

// LSTM step: G[32,512] = [A(KA); B(KB)] @ W + bias, then gate update.
// 256-thread collective: unit u = gtid&127 (cols 4u..4u+3),
// batches b0 = (gtid>>7)*16 .. +15. acc[gate][pair] = 32 ull accs.
// Weight LDG prefetch distance 2 (rolling w0,w1); act LDS prefetch distance 1
// (rolling a0..a3). Loop split KA / transition / KB with pointer bumps.
// Final act prefetch reads one row past shB (lands in adjacent buffer; unused).
template <int KA, int KB>
__device__ __forceinline__ void lstm_step(
    const float* __restrict__ W, const float* __restrict__ bias,
    const float* shA, const float* shB, float* shC, float* shOut,
    int u, int b0)
{
    ull acc[4][8];
    {
        float4 bs = *(const float4*)(bias + 4 * u);
        ull d0 = dup2(bs.x), d1 = dup2(bs.y), d2 = dup2(bs.z), d3 = dup2(bs.w);
#pragma unroll
        for (int p = 0; p < 8; ++p) {
            acc[0][p] = d0; acc[1][p] = d1; acc[2][p] = d2; acc[3][p] = d3;
        }
    }
    const float* Wk = W + 4 * u;          // weight ptr for current k
    const float* ap = shA + b0;           // act ptr for current k

    float4 w0 = __ldg((const float4*)(Wk));
    float4 w1 = __ldg((const float4*)(Wk + 512));
    ulonglong2 a0 = *(const ulonglong2*)(ap);
    ulonglong2 a1 = *(const ulonglong2*)(ap + 4);
    ulonglong2 a2 = *(const ulonglong2*)(ap + 8);
    ulonglong2 a3 = *(const ulonglong2*)(ap + 12);

#define LSTM_BODY(APN)                                                        \
    {                                                                         \
        float4 wn = __ldg((const float4*)(Wk + 1024));                        \
        const float* apn_ = (APN);                                            \
        ulonglong2 n0 = *(const ulonglong2*)(apn_);                           \
        ulonglong2 n1 = *(const ulonglong2*)(apn_ + 4);                       \
        ulonglong2 n2 = *(const ulonglong2*)(apn_ + 8);                       \
        ulonglong2 n3 = *(const ulonglong2*)(apn_ + 12);                      \
        ull wd0 = dup2(w0.x), wd1 = dup2(w0.y), wd2 = dup2(w0.z), wd3 = dup2(w0.w); \
        fma2(acc[0][0], wd0, a0.x); fma2(acc[0][1], wd0, a0.y);               \
        fma2(acc[0][2], wd0, a1.x); fma2(acc[0][3], wd0, a1.y);               \
        fma2(acc[0][4], wd0, a2.x); fma2(acc[0][5], wd0, a2.y);               \
        fma2(acc[0][6], wd0, a3.x); fma2(acc[0][7], wd0, a3.y);               \
        fma2(acc[1][0], wd1, a0.x); fma2(acc[1][1], wd1, a0.y);               \
        fma2(acc[1][2], wd1, a1.x); fma2(acc[1][3], wd1, a1.y);               \
        fma2(acc[1][4], wd1, a2.x); fma2(acc[1][5], wd1, a2.y);               \
        fma2(acc[1][6], wd1, a3.x); fma2(acc[1][7], wd1, a3.y);               \
        fma2(acc[2][0], wd2, a0.x); fma2(acc[2][1], wd2, a0.y);               \
        fma2(acc[2][2], wd2, a1.x); fma2(acc[2][3], wd2, a1.y);               \
        fma2(acc[2][4], wd2, a2.x); fma2(acc[2][5], wd2, a2.y);               \
        fma2(acc[2][6], wd2, a3.x); fma2(acc[2][7], wd2, a3.y);               \
        fma2(acc[3][0], wd3, a0.x); fma2(acc[3][1], wd3, a0.y);               \
        fma2(acc[3][2], wd3, a1.x); fma2(acc[3][3], wd3, a1.y);               \
        fma2(acc[3][4], wd3, a2.x); fma2(acc[3][5], wd3, a2.y);               \
        fma2(acc[3][6], wd3, a3.x); fma2(acc[3][7], wd3, a3.y);               \
        w0 = w1; w1 = wn; Wk += 512;                                          \
        a0 = n0; a1 = n1; a2 = n2; a3 = n3;                                   \
    }

    // KA segment (iterations 0..KA-2): next act row is ap+SS
#pragma unroll 4
    for (int k = 0; k < KA - 1; ++k) {
        LSTM_BODY(ap + SS);
        ap += SS;
    }
    // transition iteration (k = KA-1): next act row is shB row 0
    const float* bp_ = shB + b0;
    LSTM_BODY(bp_);
    ap = bp_;
    // KB segment: next act row is ap+SS (last one overshoots 1 row — safe)
#pragma unroll 8
    for (int k = 0; k < KB; ++k) {
        LSTM_BODY(ap + SS);
        ap += SS;
    }
#undef LSTM_BODY

    // epilogue: gates -> c update -> s (16 batches)
#pragma unroll
    for (int q = 0; q < 4; ++q) {
        int bq = b0 + 4 * q;
        float gi[4], gf[4], gg[4], go[4];
        unpk(acc[0][2 * q], gi[0], gi[1]); unpk(acc[0][2 * q + 1], gi[2], gi[3]);
        unpk(acc[1][2 * q], gf[0], gf[1]); unpk(acc[1][2 * q + 1], gf[2], gf[3]);
        unpk(acc[2][2 * q], gg[0], gg[1]); unpk(acc[2][2 * q + 1], gg[2], gg[3]);
        unpk(acc[3][2 * q], go[0], go[1]); unpk(acc[3][2 * q + 1], go[2], go[3]);
        float4 cv = *(const float4*)(shC + u * SS + bq);
        float cb[4] = {cv.x, cv.y, cv.z, cv.w};
        float sb[4];
#pragma unroll
        for (int j = 0; j < 4; ++j) {
            float cn = fsig(gf[j]) * cb[j] + fsig(gi[j]) * ftanh(gg[j]);
            cb[j] = cn;
            sb[j] = fsig(go[j]) * ftanh(cn);
        }
        *(float4*)(shC + u * SS + bq)   = make_float4(cb[0], cb[1], cb[2], cb[3]);
        *(float4*)(shOut + u * SS + bq) = make_float4(sb[0], sb[1], sb[2], sb[3]);
    }
}

// hp[32,32] = s[32,128] @ WhrT[128,32], weights dup'd in SMEM (stride 64).
// 256-thread collective: cg = gtid&15 -> cols 2cg,2cg+1;
// p = gtid>>4 -> batches 2p, 2p+1. Pure LDS + FFMA2.
__device__ __forceinline__ void proj_gemm(
    const float* sPW, const float* shS, float* shHdst,
    float* outp, int gtid)
{
    const int cg = gtid & 15;
    const int p  = gtid >> 4;
    ull acc0 = 0ull, acc1 = 0ull;
    const float* Wu = sPW + 4 * cg;
#pragma unroll 8
    for (int k = 0; k < 128; ++k) {
        ulonglong2 w = *(const ulonglong2*)(Wu + k * 64);  // (wc0,wc0),(wc1,wc1)
        ull a = *(const ull*)(shS + k * SS + 2 * p);       // (s_b0, s_b1)
        fma2(acc0, w.x, a);
        fma2(acc1, w.y, a);
    }
    float v00, v10, v01, v11;   // v[b][c]
    unpk(acc0, v00, v10);
    unpk(acc1, v01, v11);
    float* hp = shHdst + (2 * cg) * SS + 2 * p;
    hp[0] = v00; hp[1] = v10;
    hp[SS] = v01; hp[SS + 1] = v11;
    if (outp) {
        *(float2*)(outp + (size_t)(2 * p) * 512 + 2 * cg)     = make_float2(v00, v01);
        *(float2*)(outp + (size_t)(2 * p + 1) * 512 + 2 * cg) = make_float2(v10, v11);
    }
}

// v[8,32] = h_new[32,128] @ WpT[128,8] + bp, weights dup'd in SMEM (stride 16).
// 128 active threads: nn = gtid&7 (one col), p = gtid>>3 (batches 2p,2p+1).
__device__ __forceinline__ void wp_gemm(
    const float* __restrict__ bp, const float* sPWP,
    const float* shS, float* shV, int gtid)
{
    if (gtid >= 128) return;
    const int nn = gtid & 7;
    const int p  = gtid >> 3;
    ull acc = dup2(__ldg(&bp[nn]));
    const float* Wu = sPWP + 2 * nn;
#pragma unroll 8
    for (int k = 0; k < 128; ++k) {
        ull w = *(const ull*)(Wu + k * 16);
        ull a = *(const ull*)(shS + k * SS + 2 * p);
        fma2(acc, w, a);
    }
    float lo, hi;
    unpk(acc, lo, hi);
    shV[nn * SS + 2 * p]     = lo;
    shV[nn * SS + 2 * p + 1] = hi;
}

// quantum measurement physics for one batch element b (0..31); writes xnext
// (exact fp32 math — no approx here, feeds the recurrence)
__device__ __forceinline__ void physics(const float* shV, const float* shRHO,
                                        float* shX, int b)
{
    float Mr[2][2][2], Mi[2][2][2];
#pragma unroll
    for (int q = 0; q < 2; ++q) {
        float ar = shV[(q * 4 + 0) * SS + b];
        float ai = shV[(q * 4 + 1) * SS + b];
        float br = shV[(q * 4 + 2) * SS + b];
        float bi = shV[(q * 4 + 3) * SS + b];
        float n00 = ar * ar + ai * ai;
        float n11 = br * br + bi * bi;
        float inv = 1.0f / (n00 + n11);
        float pr = (ar * br + ai * bi) * inv;
        float pi = (ai * br - ar * bi) * inv;
        Mr[q][0][0] = n00 * inv; Mi[q][0][0] = 0.f;
        Mr[q][0][1] = pr;        Mi[q][0][1] = pi;
        Mr[q][1][0] = pr;        Mi[q][1][0] = -pi;
        Mr[q][1][1] = n11 * inv; Mi[q][1][1] = 0.f;
    }
    const float* rp = shRHO + b * 33;
    float m = 0.f;
#pragma unroll
    for (int a = 0; a < 2; ++a)
#pragma unroll
        for (int c = 0; c < 2; ++c)
#pragma unroll
            for (int b2 = 0; b2 < 2; ++b2)
#pragma unroll
                for (int d = 0; d < 2; ++d) {
                    float tr_ = Mr[0][a][c] * Mr[1][b2][d] - Mi[0][a][c] * Mi[1][b2][d];
                    float ti_ = Mr[0][a][c] * Mi[1][b2][d] + Mi[0][a][c] * Mr[1][b2][d];
                    int row = c * 2 + d, col = a * 2 + b2;
                    float rr = rp[row * 4 + col];
                    float ri = rp[16 + row * 4 + col];
                    m += tr_ * rr - ti_ * ri;
                }
    shX[0 * SS + b] = m;
#pragma unroll
    for (int q = 0; q < 2; ++q)
#pragma unroll
        for (int i = 0; i < 2; ++i)
#pragma unroll
            for (int j = 0; j < 2; ++j) {
                int base = 1 + 8 * q + 4 * i + 2 * j;
                shX[base * SS + b]       = Mr[q][i][j];
                shX[(base + 1) * SS + b] = Mi[q][i][j];
            }
}

__global__ void __launch_bounds__(NTH, 1) fused_kernel(
    const float* __restrict__ meas, const float* __restrict__ basis_r,
    const float* __restrict__ basis_i, const float* __restrict__ rho,
    const float* __restrict__ h0in, const float* __restrict__ c0in,
    const float* __restrict__ bp, float* __restrict__ out)
{
    extern __shared__ float sm[];
    float* shS   = sm + OFF_S;
    float* shCC  = sm + OFF_CC;
    float* shH0  = sm + OFF_H0;
    float* shC0  = sm + OFF_C0;
    float* shH1  = sm + OFF_H1;
    float* shC1  = sm + OFF_C1;
    float* shRHO = sm + OFF_RHO;
    float* shV   = sm + OFF_V;
    float* sPW0  = sm + OFF_PW0;
    float* sPW1  = sm + OFF_PW1;
    float* sPWP  = sm + OFF_PWP;

    const int tid = threadIdx.x;
    const int b0g = blockIdx.x * BT;

    // ---- init loads into XA ----
    for (int i = tid; i < BT; i += NTH)
        sm[OFF_XA + 0 * SS + i] = meas[b0g + i];
    for (int i = tid; i < BT * 8; i += NTH) {
        int b = i >> 3, e = i & 7;
        sm[OFF_XA + (1 + 2 * e) * SS + b] = basis_r[(size_t)(b0g + b) * 8 + e];
        sm[OFF_XA + (2 + 2 * e) * SS + b] = basis_i[(size_t)(b0g + b) * 8 + e];
    }
    for (int i = tid; i < BT * 32; i += NTH) {
        int b = i >> 5, e = i & 31;
        shRHO[b * 33 + e] = rho[(size_t)(b0g + b) * 32 + e];
    }
    for (int i = tid; i < BT * 128; i += NTH) {
        int b = i >> 7, u = i & 127;
        sm[OFF_HCA + u * SS + b] = h0in[(size_t)(b0g + b) * 128 + u];
        shCC[u * SS + b]         = c0in[(size_t)(b0g + b) * 128 + u];
    }
    // zero H0, C0, H1, C1 (320 contiguous rows)
    for (int i = tid; i < 320 * SS; i += NTH)
        sm[OFF_H0 + i] = 0.f;
    // fill dup'd small-GEMM weights (once per CTA)
    for (int i = tid; i < 128 * 32; i += NTH) {
        int k = i >> 5, n = i & 31;
        float v0 = __ldg(&g_Whr0T[i]);
        float v1 = __ldg(&g_Whr1T[i]);
        sPW0[k * 64 + 2 * n] = v0; sPW0[k * 64 + 2 * n + 1] = v0;
        sPW1[k * 64 + 2 * n] = v1; sPW1[k * 64 + 2 * n + 1] = v1;
    }
    for (int i = tid; i < 128 * 8; i += NTH) {
        int k = i >> 3, n = i & 7;
        float v = __ldg(&g_WpT[i]);
        sPWP[k * 16 + 2 * n] = v; sPWP[k * 16 + 2 * n + 1] = v;
    }
    __syncthreads();

    const bool isA = (tid < 256);
    const int gtid = tid & 255;
    const int u  = gtid & 127;
    const int b0 = (gtid >> 7) * 16;

    float* xcur = sm + OFF_XA;
    float* xnxt = sm + OFF_XB;
    float* hcur = sm + OFF_HCA;
    float* hnxt = sm + OFF_HCB;

    for (int t = 0; t < 16; ++t) {
        if (isA) {
            // group A: cell chain (produces x_{t+1} into xnxt, h_new into hnxt)
            if (t < 15) {
                lstm_step<17, 128>(g_Wc, g_bc, xcur, hcur, shCC, hnxt, u, b0);
                BARA();
                wp_gemm(bp, sPWP, hnxt, shV, gtid);
                BARA();
                if (gtid < BT) physics(shV, shRHO, xnxt, gtid);
            }
        } else {
            // group B: output chain for step t (reads xcur only)
            lstm_step<17, 32>(g_W0, g_b0, xcur, shH0, shC0, shS, u, b0);
            BARB();
            proj_gemm(sPW0, shS, shH0, nullptr, gtid);
            BARB();
            lstm_step<32, 32>(g_W1, g_b1, shH0, shH1, shC1, shS, u, b0);
            BARB();
            proj_gemm(sPW1, shS, shH1,
                      out + (size_t)b0g * 512 + (size_t)t * 32, gtid);
        }
        __syncthreads();
        if (t < 15) {
            float* tp = hcur; hcur = hnxt; hnxt = tp;
            float* tx = xcur; xcur = xnxt; xnxt = tx;
        }
    }
}

extern "C" void kernel_launch(void* const* d_in, const int* in_sizes, int n_in,
                              void* d_out, int out_size)
{
    const float* meas   = (const float*)d_in[0];
    const float* br     = (const float*)d_in[1];
    const float* bi     = (const float*)d_in[2];
    const float* rho    = (const float*)d_in[3];
    const float* h0     = (const float*)d_in[4];
    const float* c0     = (const float*)d_in[5];
    const float* Wihc   = (const float*)d_in[6];
    const float* Whhc   = (const float*)d_in[7];
    const float* bihc   = (const float*)d_in[8];
    const float* bhhc   = (const float*)d_in[9];
    const float* Wp     = (const float*)d_in[10];
    const float* bp     = (const float*)d_in[11];
    const float* Wih0   = (const float*)d_in[12];
    const float* Whh0   = (const float*)d_in[13];
    const float* bih0   = (const float*)d_in[14];
    const float* bhh0   = (const float*)d_in[15];
    const float* Whr0   = (const float*)d_in[16];
    const float* Wih1   = (const float*)d_in[17];
    const float* Whh1   = (const float*)d_in[18];
    const float* bih1   = (const float*)d_in[19];
    const float* bhh1   = (const float*)d_in[20];
    const float* Whr1   = (const float*)d_in[21];

    int B = in_sizes[0];
    int nblocks = B / BT;

    cudaFuncSetAttribute(fused_kernel,
                         cudaFuncAttributeMaxDynamicSharedMemorySize,
                         SMEM_BYTES);

    prep_kernel<<<128, 256>>>(Wihc, Whhc, bihc, bhhc, Wp,
                              Wih0, Whh0, bih0, bhh0, Whr0,
                              Wih1, Whh1, bih1, bhh1, Whr1);

    fused_kernel<<<nblocks, NTH, SMEM_BYTES>>>(
        meas, br, bi, rho, h0, c0, bp, (float*)d_out);
}

// round 14
// speedup vs baseline: 1.2592x; 1.0253x over previous
#include <cuda_runtime.h>
#include <cuda_bf16.h>

// ---------------------------------------------------------------------------
// Fused LSTMMeasurementPredictor — round 14: tensor-core GEMMs
//   B=131072, H=128, NQ=2, P=32, D_IN=17, T=16
// All three LSTM GEMMs run as G[512,32] = W[512,K] @ X[K,32] on the tensor
// pipe via mma.sync.m16n8k16 (bf16) with a 3-term bf16 split for fp32-like
// accuracy: W,X -> (hi,lo) bf16; acc += Wh*Xh + Wh*Xl + Wl*Xh.
// Weights pre-packed in A-fragment layout by prep_kernel (1 LDG.128 = 1 frag).
// Activations converted fp32 -> bf16 hi/lo per step into fragment-layout SMEM.
// Accumulators staged through SMEM G buffer; gate epilogue (tanh.approx),
// proj/wp/physics as before. Sequential phase structure, 512 threads.
// ---------------------------------------------------------------------------

#define NTH 512
#define BT  32
#define SS  36   // padded row stride for [K][32] state buffers

// smem layout (floats)
constexpr int OFF_XA  = 0;                    // 17  rows : x ping
constexpr int OFF_XB  = OFF_XA  + 17  * SS;   // 17  rows : x pong
constexpr int OFF_HCA = OFF_XB  + 17  * SS;   // 128 rows : cell h ping
constexpr int OFF_HCB = OFF_HCA + 128 * SS;   // 128 rows : cell h pong
constexpr int OFF_S   = OFF_HCB + 128 * SS;   // 128 rows : s staging
constexpr int OFF_CC  = OFF_S   + 128 * SS;   // 128 rows : cell c
constexpr int OFF_C0  = OFF_CC  + 128 * SS;   // 128 rows : lstm0 c
constexpr int OFF_C1  = OFF_C0  + 128 * SS;   // 128 rows : lstm1 c
constexpr int OFF_H0  = OFF_C1  + 128 * SS;   // 32  rows : lstm0 proj h
constexpr int OFF_H1  = OFF_H0  + 32  * SS;   // 32  rows : lstm1 proj h
constexpr int OFF_RHO = OFF_H1  + 32  * SS;   // 32*33    : rho
constexpr int OFF_V   = OFF_RHO + 32 * 33;    // 8 rows   : projector v
constexpr int OFF_G   = OFF_V   + 8 * SS;     // 512 rows x 36 : gate staging
constexpr int OFF_XCH = OFF_G   + 512 * 36;   // 2560 u32 : X hi frags (10 ch)
constexpr int OFF_XCL = OFF_XCH + 2560;       // 2560 u32 : X lo frags
constexpr int SMEM_FLOATS = OFF_XCL + 2560;
constexpr int SMEM_BYTES  = SMEM_FLOATS * 4;  // ~224 KB

// A-fragment-packed weights. Index: ((chunk*32 + mfrag)*32 + lane)*4 + r,
// 4 u32 regs = one m16k16 bf16 A frag (uint4 per lane). One zero pad chunk.
__device__ __align__(16) unsigned g_WcH[11 * 4096];
__device__ __align__(16) unsigned g_WcL[11 * 4096];
__device__ __align__(16) unsigned g_W0H[5 * 4096];
__device__ __align__(16) unsigned g_W0L[5 * 4096];
__device__ __align__(16) unsigned g_W1H[5 * 4096];
__device__ __align__(16) unsigned g_W1L[5 * 4096];
__device__ __align__(16) float g_bc[512];   // gate-interleaved (j = 4u+g)
__device__ __align__(16) float g_b0[512];
__device__ __align__(16) float g_b1[512];
__device__ __align__(16) float g_Whr0T[128 * 32];
__device__ __align__(16) float g_Whr1T[128 * 32];
__device__ __align__(16) float g_WpT[128 * 8];

__device__ __forceinline__ void split2(float x0, float x1,
                                       unsigned& hp, unsigned& lp) {
    __nv_bfloat16 h0 = __float2bfloat16(x0);
    __nv_bfloat16 h1 = __float2bfloat16(x1);
    float l0f = x0 - __bfloat162float(h0);
    float l1f = x1 - __bfloat162float(h1);
    __nv_bfloat16 l0 = __float2bfloat16(l0f);
    __nv_bfloat16 l1 = __float2bfloat16(l1f);
    hp = ((unsigned)__bfloat16_as_ushort(h1) << 16) | __bfloat16_as_ushort(h0);
    lp = ((unsigned)__bfloat16_as_ushort(l1) << 16) | __bfloat16_as_ushort(l0);
}

__global__ void prep_kernel(
    const float* __restrict__ Wihc, const float* __restrict__ Whhc,
    const float* __restrict__ bihc, const float* __restrict__ bhhc,
    const float* __restrict__ Wp,
    const float* __restrict__ Wih0, const float* __restrict__ Whh0,
    const float* __restrict__ bih0, const float* __restrict__ bhh0,
    const float* __restrict__ Whr0,
    const float* __restrict__ Wih1, const float* __restrict__ Whh1,
    const float* __restrict__ bih1, const float* __restrict__ bhh1,
    const float* __restrict__ Whr1)
{
    int i0 = blockIdx.x * blockDim.x + threadIdx.x;
    int stride = gridDim.x * blockDim.x;

    // cell: logical W[j][k], j=4u+g -> orig row g*128+u; K=145
    for (int i = i0; i < 11 * 4096; i += stride) {
        int r = i & 3, lane = (i >> 2) & 31, mf = (i >> 7) & 31, ch = i >> 12;
        int gr = lane >> 2, q = lane & 3;
        int j = mf * 16 + gr + (r & 1) * 8;
        int k = ch * 16 + 2 * q + (r >> 1) * 8;
        int u = j >> 2, g = j & 3, orow = g * 128 + u;
        float w0 = (k < 17) ? Wihc[orow * 17 + k]
                 : (k < 145 ? Whhc[orow * 128 + (k - 17)] : 0.f);
        int k1 = k + 1;
        float w1 = (k1 < 17) ? Wihc[orow * 17 + k1]
                 : (k1 < 145 ? Whhc[orow * 128 + (k1 - 17)] : 0.f);
        unsigned hp, lp; split2(w0, w1, hp, lp);
        g_WcH[i] = hp; g_WcL[i] = lp;
    }
    // lstm0: [x(17); hp0(32)] K=49
    for (int i = i0; i < 5 * 4096; i += stride) {
        int r = i & 3, lane = (i >> 2) & 31, mf = (i >> 7) & 31, ch = i >> 12;
        int gr = lane >> 2, q = lane & 3;
        int j = mf * 16 + gr + (r & 1) * 8;
        int k = ch * 16 + 2 * q + (r >> 1) * 8;
        int u = j >> 2, g = j & 3, orow = g * 128 + u;
        float w0 = (k < 17) ? Wih0[orow * 17 + k]
                 : (k < 49 ? Whh0[orow * 32 + (k - 17)] : 0.f);
        int k1 = k + 1;
        float w1 = (k1 < 17) ? Wih0[orow * 17 + k1]
                 : (k1 < 49 ? Whh0[orow * 32 + (k1 - 17)] : 0.f);
        unsigned hp, lp; split2(w0, w1, hp, lp);
        g_W0H[i] = hp; g_W0L[i] = lp;
    }
    // lstm1: [hp0(32); hp1(32)] K=64
    for (int i = i0; i < 5 * 4096; i += stride) {
        int r = i & 3, lane = (i >> 2) & 31, mf = (i >> 7) & 31, ch = i >> 12;
        int gr = lane >> 2, q = lane & 3;
        int j = mf * 16 + gr + (r & 1) * 8;
        int k = ch * 16 + 2 * q + (r >> 1) * 8;
        int u = j >> 2, g = j & 3, orow = g * 128 + u;
        float w0 = (k < 32) ? Wih1[orow * 32 + k]
                 : (k < 64 ? Whh1[orow * 32 + (k - 32)] : 0.f);
        int k1 = k + 1;
        float w1 = (k1 < 32) ? Wih1[orow * 32 + k1]
                 : (k1 < 64 ? Whh1[orow * 32 + (k1 - 32)] : 0.f);
        unsigned hp, lp; split2(w0, w1, hp, lp);
        g_W1H[i] = hp; g_W1L[i] = lp;
    }
    for (int i = i0; i < 512; i += stride) {
        int u = i >> 2, g = i & 3, j = g * 128 + u;
        g_bc[i] = bihc[j] + bhhc[j];
        g_b0[i] = bih0[j] + bhh0[j];
        g_b1[i] = bih1[j] + bhh1[j];
    }
    for (int i = i0; i < 128 * 32; i += stride) {
        int k = i >> 5, n = i & 31;
        g_Whr0T[i] = Whr0[n * 128 + k];
        g_Whr1T[i] = Whr1[n * 128 + k];
    }
    for (int i = i0; i < 128 * 8; i += stride) {
        int k = i >> 3, n = i & 7;
        g_WpT[i] = Wp[n * 128 + k];
    }
}

// ---------------------------------------------------------------------------
typedef unsigned long long ull;

__device__ __forceinline__ void fma2(ull& acc, ull a, ull b) {
    asm("fma.rn.f32x2 %0, %1, %2, %0;" : "+l"(acc) : "l"(a), "l"(b));
}
__device__ __forceinline__ ull dup2(float x) {
    ull r;
    asm("mov.b64 %0, {%1, %1};" : "=l"(r) : "f"(x));
    return r;
}
__device__ __forceinline__ void unpk(ull v, float& lo, float& hi) {
    asm("mov.b64 {%0, %1}, %2;" : "=f"(lo), "=f"(hi) : "l"(v));
}
__device__ __forceinline__ float htanh(float x) {
    float y;
    asm("tanh.approx.f32 %0, %1;" : "=f"(y) : "f"(x));
    return y;
}
__device__ __forceinline__ float fsig(float x) {
    return fmaf(0.5f, htanh(0.5f * x), 0.5f);
}

__device__ __forceinline__ void mma16816(float& d0, float& d1, float& d2,
                                         float& d3, const uint4& a,
                                         unsigned b0, unsigned b1) {
    asm volatile(
        "mma.sync.aligned.m16n8k16.row.col.f32.bf16.bf16.f32 "
        "{%0,%1,%2,%3}, {%4,%5,%6,%7}, {%8,%9}, {%0,%1,%2,%3};"
        : "+f"(d0), "+f"(d1), "+f"(d2), "+f"(d3)
        : "r"(a.x), "r"(a.y), "r"(a.z), "r"(a.w), "r"(b0), "r"(b1));
}

// fp32 -> bf16 hi/lo conversion of X[K,32] into fragment layout:
// XC[(ch*32 + n)*8 + e] = bf16x2(X[ch*16+2e][n], X[ch*16+2e+1][n])
template <int KA, int KB, int CH>
__device__ __forceinline__ void conv_bf16(
    const float* srcA, const float* srcB,
    unsigned* XCH, unsigned* XCL, int tid)
{
    for (int i = tid; i < CH * 256; i += NTH) {
        int e = i & 7, n = (i >> 3) & 31, ch = i >> 8;
        int k = ch * 16 + 2 * e;
        float x0 = (k < KA) ? srcA[k * SS + n]
                 : (k < KA + KB ? srcB[(k - KA) * SS + n] : 0.f);
        int k1 = k + 1;
        float x1 = (k1 < KA) ? srcA[k1 * SS + n]
                 : (k1 < KA + KB ? srcB[(k1 - KA) * SS + n] : 0.f);
        unsigned hp, lp; split2(x0, x1, hp, lp);
        XCH[i] = hp; XCL[i] = lp;
    }
}

// G[512,32] = W @ X via mma.sync, 3-term bf16 split, all 16 warps.
// Warp w handles rows 32w..32w+31 (mfrags 2w, 2w+1). A frags prefetched
// distance 1 (arrays have one zero pad chunk). Result staged to G (stride 36).
template <int CH>
__device__ __forceinline__ void mma_gemm(
    const unsigned* __restrict__ WH, const unsigned* __restrict__ WL,
    const unsigned* XCH, const unsigned* XCL, float* G, int tid)
{
    const int w = tid >> 5, lane = tid & 31, gr = lane >> 2, q = lane & 3;
    float d[2][4][4];
#pragma unroll
    for (int m = 0; m < 2; ++m)
#pragma unroll
        for (int nf = 0; nf < 4; ++nf)
#pragma unroll
            for (int r = 0; r < 4; ++r) d[m][nf][r] = 0.f;

    const uint4* pH = (const uint4*)WH;
    const uint4* pL = (const uint4*)WL;
    const int base0 = 2 * w * 32 + lane;
    uint4 aH0 = pH[base0], aH1 = pH[base0 + 32];
    uint4 aL0 = pL[base0], aL1 = pL[base0 + 32];

#pragma unroll
    for (int ch = 0; ch < CH; ++ch) {
        int nb = (ch + 1) * 1024 + base0;       // pad chunk makes this safe
        uint4 nH0 = pH[nb], nH1 = pH[nb + 32];
        uint4 nL0 = pL[nb], nL1 = pL[nb + 32];
#pragma unroll
        for (int nf = 0; nf < 4; ++nf) {
            int xb = (ch * 32 + nf * 8 + gr) * 8;
            unsigned bh0 = XCH[xb + q], bh1 = XCH[xb + q + 4];
            unsigned bl0 = XCL[xb + q], bl1 = XCL[xb + q + 4];
            mma16816(d[0][nf][0], d[0][nf][1], d[0][nf][2], d[0][nf][3], aH0, bh0, bh1);
            mma16816(d[1][nf][0], d[1][nf][1], d[1][nf][2], d[1][nf][3], aH1, bh0, bh1);
            mma16816(d[0][nf][0], d[0][nf][1], d[0][nf][2], d[0][nf][3], aH0, bl0, bl1);
            mma16816(d[1][nf][0], d[1][nf][1], d[1][nf][2], d[1][nf][3], aH1, bl0, bl1);
            mma16816(d[0][nf][0], d[0][nf][1], d[0][nf][2], d[0][nf][3], aL0, bh0, bh1);
            mma16816(d[1][nf][0], d[1][nf][1], d[1][nf][2], d[1][nf][3], aL1, bh0, bh1);
        }
        aH0 = nH0; aH1 = nH1; aL0 = nL0; aL1 = nL1;
    }
#pragma unroll
    for (int m = 0; m < 2; ++m) {
        int R = w * 32 + m * 16;
#pragma unroll
        for (int nf = 0; nf < 4; ++nf) {
            int col = nf * 8 + 2 * q;
            *(float2*)(G + (R + gr) * 36 + col)     = make_float2(d[m][nf][0], d[m][nf][1]);
            *(float2*)(G + (R + gr + 8) * 36 + col) = make_float2(d[m][nf][2], d[m][nf][3]);
        }
    }
}

// gate epilogue: thread = unit u = tid>>2, batches bb..bb+7 (bb=(tid&3)*8)
__device__ __forceinline__ void gate_epilogue(
    const float* __restrict__ bias, const float* G,
    float* C, float* Sout, int tid)
{
    const int u = tid >> 2;
    const int bb = (tid & 3) * 8;
    float4 bs = __ldg((const float4*)(bias + 4 * u));
    const float bsa[4] = {bs.x, bs.y, bs.z, bs.w};
    float gv[4][8];
#pragma unroll
    for (int g = 0; g < 4; ++g) {
        const float* gp = G + (4 * u + g) * 36 + bb;
        float4 v0 = *(const float4*)gp;
        float4 v1 = *(const float4*)(gp + 4);
        gv[g][0] = v0.x + bsa[g]; gv[g][1] = v0.y + bsa[g];
        gv[g][2] = v0.z + bsa[g]; gv[g][3] = v0.w + bsa[g];
        gv[g][4] = v1.x + bsa[g]; gv[g][5] = v1.y + bsa[g];
        gv[g][6] = v1.z + bsa[g]; gv[g][7] = v1.w + bsa[g];
    }
    float* cp = C + u * SS + bb;
    float4 c0 = *(const float4*)cp;
    float4 c1 = *(const float4*)(cp + 4);
    float cb[8] = {c0.x, c0.y, c0.z, c0.w, c1.x, c1.y, c1.z, c1.w};
    float sb[8];
#pragma unroll
    for (int j = 0; j < 8; ++j) {
        float cn = fsig(gv[1][j]) * cb[j] + fsig(gv[0][j]) * htanh(gv[2][j]);
        cb[j] = cn;
        sb[j] = fsig(gv[3][j]) * htanh(cn);
    }
    *(float4*)cp       = make_float4(cb[0], cb[1], cb[2], cb[3]);
    *(float4*)(cp + 4) = make_float4(cb[4], cb[5], cb[6], cb[7]);
    float* op = Sout + u * SS + bb;
    *(float4*)op       = make_float4(sb[0], sb[1], sb[2], sb[3]);
    *(float4*)(op + 4) = make_float4(sb[4], sb[5], sb[6], sb[7]);
}

// hp[32,32] = s[32? no: s[128] rows] @ WhrT[128,32]. 512 threads:
// c2 = tid&15 -> cols 2c2,2c2+1; b = tid>>4 (0..31).
__device__ __forceinline__ void proj_gemm(
    const float* __restrict__ WT, const float* shS, float* dst,
    float* outp, int tid)
{
    const int c2 = tid & 15;
    const int b  = tid >> 4;
    ull acc = 0ull;
#pragma unroll 8
    for (int k = 0; k < 128; ++k) {
        ull w = __ldg((const ull*)(WT + k * 32 + 2 * c2));
        ull a = dup2(shS[k * SS + b]);
        fma2(acc, w, a);
    }
    float v0, v1;
    unpk(acc, v0, v1);
    dst[(2 * c2) * SS + b]     = v0;
    dst[(2 * c2 + 1) * SS + b] = v1;
    if (outp)
        *(float2*)(outp + (size_t)b * 512 + 2 * c2) = make_float2(v0, v1);
}

// v[8,32] = h_new[128,32rows...] : v[nn][b] = sum_k h[k][b] WpT[k][nn] + bp[nn]
__device__ __forceinline__ void wp_gemm(
    const float* __restrict__ bp, const float* shH, float* shV, int tid)
{
    if (tid >= 256) return;
    const int nn = tid >> 5;
    const int b  = tid & 31;
    float a = __ldg(&bp[nn]);
#pragma unroll 8
    for (int k = 0; k < 128; ++k)
        a += shH[k * SS + b] * __ldg(&g_WpT[k * 8 + nn]);
    shV[nn * SS + b] = a;
}

// quantum measurement physics for one batch element b (0..31); writes xnext
__device__ __forceinline__ void physics(const float* shV, const float* shRHO,
                                        float* shX, int b)
{
    float Mr[2][2][2], Mi[2][2][2];
#pragma unroll
    for (int q = 0; q < 2; ++q) {
        float ar = shV[(q * 4 + 0) * SS + b];
        float ai = shV[(q * 4 + 1) * SS + b];
        float br = shV[(q * 4 + 2) * SS + b];
        float bi = shV[(q * 4 + 3) * SS + b];
        float n00 = ar * ar + ai * ai;
        float n11 = br * br + bi * bi;
        float inv = 1.0f / (n00 + n11);
        float pr = (ar * br + ai * bi) * inv;
        float pi = (ai * br - ar * bi) * inv;
        Mr[q][0][0] = n00 * inv; Mi[q][0][0] = 0.f;
        Mr[q][0][1] = pr;        Mi[q][0][1] = pi;
        Mr[q][1][0] = pr;        Mi[q][1][0] = -pi;
        Mr[q][1][1] = n11 * inv; Mi[q][1][1] = 0.f;
    }
    const float* rp = shRHO + b * 33;
    float m = 0.f;
#pragma unroll
    for (int a = 0; a < 2; ++a)
#pragma unroll
        for (int c = 0; c < 2; ++c)
#pragma unroll
            for (int b2 = 0; b2 < 2; ++b2)
#pragma unroll
                for (int d = 0; d < 2; ++d) {
                    float tr_ = Mr[0][a][c] * Mr[1][b2][d] - Mi[0][a][c] * Mi[1][b2][d];
                    float ti_ = Mr[0][a][c] * Mi[1][b2][d] + Mi[0][a][c] * Mr[1][b2][d];
                    int row = c * 2 + d, col = a * 2 + b2;
                    float rr = rp[row * 4 + col];
                    float ri = rp[16 + row * 4 + col];
                    m += tr_ * rr - ti_ * ri;
                }
    shX[0 * SS + b] = m;
#pragma unroll
    for (int q = 0; q < 2; ++q)
#pragma unroll
        for (int i = 0; i < 2; ++i)
#pragma unroll
            for (int j = 0; j < 2; ++j) {
                int base = 1 + 8 * q + 4 * i + 2 * j;
                shX[base * SS + b]       = Mr[q][i][j];
                shX[(base + 1) * SS + b] = Mi[q][i][j];
            }
}

__global__ void __launch_bounds__(NTH, 1) fused_kernel(
    const float* __restrict__ meas, const float* __restrict__ basis_r,
    const float* __restrict__ basis_i, const float* __restrict__ rho,
    const float* __restrict__ h0in, const float* __restrict__ c0in,
    const float* __restrict__ bp, float* __restrict__ out)
{
    extern __shared__ float sm[];
    float* shS   = sm + OFF_S;
    float* shCC  = sm + OFF_CC;
    float* shC0  = sm + OFF_C0;
    float* shC1  = sm + OFF_C1;
    float* shH0  = sm + OFF_H0;
    float* shH1  = sm + OFF_H1;
    float* shRHO = sm + OFF_RHO;
    float* shV   = sm + OFF_V;
    float* shG   = sm + OFF_G;
    unsigned* XCH = (unsigned*)(sm + OFF_XCH);
    unsigned* XCL = (unsigned*)(sm + OFF_XCL);

    const int tid = threadIdx.x;
    const int b0g = blockIdx.x * BT;

    // ---- init loads into XA ----
    for (int i = tid; i < BT; i += NTH)
        sm[OFF_XA + 0 * SS + i] = meas[b0g + i];
    for (int i = tid; i < BT * 8; i += NTH) {
        int b = i >> 3, e = i & 7;
        sm[OFF_XA + (1 + 2 * e) * SS + b] = basis_r[(size_t)(b0g + b) * 8 + e];
        sm[OFF_XA + (2 + 2 * e) * SS + b] = basis_i[(size_t)(b0g + b) * 8 + e];
    }
    for (int i = tid; i < BT * 32; i += NTH) {
        int b = i >> 5, e = i & 31;
        shRHO[b * 33 + e] = rho[(size_t)(b0g + b) * 32 + e];
    }
    for (int i = tid; i < BT * 128; i += NTH) {
        int b = i >> 7, u = i & 127;
        sm[OFF_HCA + u * SS + b] = h0in[(size_t)(b0g + b) * 128 + u];
        shCC[u * SS + b]         = c0in[(size_t)(b0g + b) * 128 + u];
    }
    // zero CC..H1 region's companions: C0, C1, H0, H1 (contiguous from OFF_C0)
    for (int i = tid; i < (128 + 128 + 32 + 32) * SS; i += NTH)
        sm[OFF_C0 + i] = 0.f;
    __syncthreads();

    float* xcur = sm + OFF_XA;
    float* xnxt = sm + OFF_XB;
    float* hcur = sm + OFF_HCA;
    float* hnxt = sm + OFF_HCB;

    for (int t = 0; t < 16; ++t) {
        // ---- lstm0: X = [x(17); h0(32)], K=49 -> 4 chunks ----
        conv_bf16<17, 32, 4>(xcur, shH0, XCH, XCL, tid);
        __syncthreads();
        mma_gemm<4>(g_W0H, g_W0L, XCH, XCL, shG, tid);
        __syncthreads();
        gate_epilogue(g_b0, shG, shC0, shS, tid);
        __syncthreads();
        proj_gemm(g_Whr0T, shS, shH0, nullptr, tid);
        __syncthreads();
        // ---- lstm1: X = [hp0(32); hp1(32)], K=64 -> 4 chunks ----
        conv_bf16<32, 32, 4>(shH0, shH1, XCH, XCL, tid);
        __syncthreads();
        mma_gemm<4>(g_W1H, g_W1L, XCH, XCL, shG, tid);
        __syncthreads();
        gate_epilogue(g_b1, shG, shC1, shS, tid);
        __syncthreads();
        proj_gemm(g_Whr1T, shS, shH1,
                  out + (size_t)b0g * 512 + (size_t)t * 32, tid);
        __syncthreads();

        if (t < 15) {
            // ---- cell: X = [x(17); h(128)], K=145 -> 10 chunks ----
            conv_bf16<17, 128, 10>(xcur, hcur, XCH, XCL, tid);
            __syncthreads();
            mma_gemm<10>(g_WcH, g_WcL, XCH, XCL, shG, tid);
            __syncthreads();
            gate_epilogue(g_bc, shG, shCC, hnxt, tid);
            __syncthreads();
            wp_gemm(bp, hnxt, shV, tid);
            __syncthreads();
            if (tid < BT) physics(shV, shRHO, xnxt, tid);
            __syncthreads();
            float* tp = hcur; hcur = hnxt; hnxt = tp;
            float* tx = xcur; xcur = xnxt; xnxt = tx;
        }
    }
}

extern "C" void kernel_launch(void* const* d_in, const int* in_sizes, int n_in,
                              void* d_out, int out_size)
{
    const float* meas   = (const float*)d_in[0];
    const float* br     = (const float*)d_in[1];
    const float* bi     = (const float*)d_in[2];
    const float* rho    = (const float*)d_in[3];
    const float* h0     = (const float*)d_in[4];
    const float* c0     = (const float*)d_in[5];
    const float* Wihc   = (const float*)d_in[6];
    const float* Whhc   = (const float*)d_in[7];
    const float* bihc   = (const float*)d_in[8];
    const float* bhhc   = (const float*)d_in[9];
    const float* Wp     = (const float*)d_in[10];
    const float* bp     = (const float*)d_in[11];
    const float* Wih0   = (const float*)d_in[12];
    const float* Whh0   = (const float*)d_in[13];
    const float* bih0   = (const float*)d_in[14];
    const float* bhh0   = (const float*)d_in[15];
    const float* Whr0   = (const float*)d_in[16];
    const float* Wih1   = (const float*)d_in[17];
    const float* Whh1   = (const float*)d_in[18];
    const float* bih1   = (const float*)d_in[19];
    const float* bhh1   = (const float*)d_in[20];
    const float* Whr1   = (const float*)d_in[21];

    int B = in_sizes[0];
    int nblocks = B / BT;

    cudaFuncSetAttribute(fused_kernel,
                         cudaFuncAttributeMaxDynamicSharedMemorySize,
                         SMEM_BYTES);

    prep_kernel<<<256, 256>>>(Wihc, Whhc, bihc, bhhc, Wp,
                              Wih0, Whh0, bih0, bhh0, Whr0,
                              Wih1, Whh1, bih1, bhh1, Whr1);

    fused_kernel<<<nblocks, NTH, SMEM_BYTES>>>(
        meas, br, bi, rho, h0, c0, bp, (float*)d_out);
}